// round 1
// baseline (speedup 1.0000x reference)
#include <cuda_runtime.h>
#include <cstdint>

#define NB_B 128
#define NB_T 200
#define NB_NC 3
#define NB_NB 2
#define NB_D 512
#define NB_DH 256
#define NGROUP (NB_B*NB_T*NB_NC)      /* 76800 */
#define NBOX   (NGROUP*NB_NB)         /* 153600 */

// Scratch: H [NBOX, 256] fp32 (tf32-rounded), meta [NBOX, 8]
__device__ float g_H[(size_t)NBOX * NB_DH];
__device__ float g_meta[(size_t)NBOX * 8];

__device__ __forceinline__ float to_tf32(float x){
    uint32_t u; asm("cvt.rna.tf32.f32 %0, %1;" : "=r"(u) : "f"(x));
    return __uint_as_float(u);
}

__device__ __forceinline__ float gelu_exact(float x){
    return 0.5f * x * (1.0f + erff(x * 0.70710678118654752440f));
}

// ---------------------------------------------------------------------------
// Kernel 1: per (b,t,cam) group of 2 boxes: sort, features, geom@W1 -> LN ->
// GELU -> H scratch; dist tokens -> out; meta -> scratch.
// ---------------------------------------------------------------------------
__global__ __launch_bounds__(256) void k_features(
    const float* __restrict__ box,
    const float* __restrict__ W1, const float* __restrict__ b1,
    const float* __restrict__ lng, const float* __restrict__ lnb,
    const float* __restrict__ dist_w, const float* __restrict__ dist_b,
    float* __restrict__ out)
{
    __shared__ float sW1[10*256];
    __shared__ float redA[8], redB[8], redC[8], redD[8];
    __shared__ float bc[4];

    const int tid  = threadIdx.x;
    const int lane = tid & 31;
    const int warp = tid >> 5;
    const int g    = blockIdx.x;

    for (int i = tid; i < 2560; i += 256) sW1[i] = W1[i];

    // ---- group preprocessing (redundant per thread; broadcast loads) ----
    const float* bd = box + (size_t)g * 12;
    float raw[12];
#pragma unroll
    for (int i = 0; i < 12; i++) raw[i] = __ldg(bd + i);

    const float nrm0 = 640.0f, nrm1 = 400.0f;
    float c0[4], c1[4];
    c0[0] = raw[0]/nrm0;  c0[1] = raw[1]/nrm1;  c0[2] = raw[2]/nrm0;  c0[3] = raw[3]/nrm1;
    c1[0] = raw[6]/nrm0;  c1[1] = raw[7]/nrm1;  c1[2] = raw[8]/nrm0;  c1[3] = raw[9]/nrm1;
    float cat0 = raw[4],  conf0 = raw[5];
    float cat1 = raw[10], conf1 = raw[11];

    float s0 = ((c0[0]+c0[1])+c0[2])+c0[3];
    float s1 = ((c1[0]+c1[1])+c1[2])+c1[3];
    float p0 = (s0 != 0.0f) ? 1.0f : 0.0f;
    float p1 = (s1 != 0.0f) ? 1.0f : 0.0f;
    float key0 = cat0 + (1.0f - p0)*1000.0f;
    float key1 = cat1 + (1.0f - p1)*1000.0f;
    const bool swp = (key1 < key0);   // stable ascending argsort over 2 elems

    float sc[2][4], scat[2], sconf[2], spres[2];
#pragma unroll
    for (int k = 0; k < 4; k++){
        sc[0][k] = swp ? c1[k] : c0[k];
        sc[1][k] = swp ? c0[k] : c1[k];
    }
    scat[0]  = swp ? cat1 : cat0;   scat[1]  = swp ? cat0 : cat1;
    sconf[0] = swp ? conf1 : conf0; sconf[1] = swp ? conf0 : conf1;
    spres[0] = swp ? p1 : p0;       spres[1] = swp ? p0 : p1;

    float feat[2][10], cxs[2], cys[2];
#pragma unroll
    for (int s = 0; s < 2; s++){
        float x1 = sc[s][0], y1 = sc[s][1], x2 = sc[s][2], y2 = sc[s][3];
        float w  = x2 - x1, h = y2 - y1;
        float cx = (x1 + x2) * 0.5f, cy = (y1 + y2) * 0.5f;
        float area = w * h;
        float asp  = w / (h + 1e-6f);
        feat[s][0]=x1; feat[s][1]=y1; feat[s][2]=x2; feat[s][3]=y2;
        feat[s][4]=w;  feat[s][5]=h;  feat[s][6]=cx; feat[s][7]=cy;
        feat[s][8]=area; feat[s][9]=asp;
        cxs[s]=cx; cys[s]=cy;
    }
    float dx = cxs[0]-cxs[1], dy = cys[0]-cys[1];
    float dist = sqrtf(dx*dx + dy*dy);

    __syncthreads();   // W1 in smem

    // ---- geom @ W1 + b1 (one output column per thread, 2 boxes) ----
    float bias = b1[tid];
    float v0 = bias, v1 = bias;
#pragma unroll
    for (int f = 0; f < 10; f++){
        float w = sW1[f*256 + tid];
        v0 = fmaf(feat[0][f], w, v0);
        v1 = fmaf(feat[1][f], w, v1);
    }

    // ---- mean reduce (both boxes) ----
    float a0 = v0, a1 = v1;
#pragma unroll
    for (int o = 16; o; o >>= 1){
        a0 += __shfl_down_sync(0xffffffffu, a0, o);
        a1 += __shfl_down_sync(0xffffffffu, a1, o);
    }
    if (lane == 0){ redA[warp] = a0; redB[warp] = a1; }
    __syncthreads();
    if (tid == 0){
        float t0 = 0.f, t1 = 0.f;
#pragma unroll
        for (int i = 0; i < 8; i++){ t0 += redA[i]; t1 += redB[i]; }
        bc[0] = t0 * (1.0f/256.0f); bc[1] = t1 * (1.0f/256.0f);
    }
    __syncthreads();
    float mu0 = bc[0], mu1 = bc[1];
    float d0 = v0 - mu0, d1 = v1 - mu1;

    // ---- variance reduce ----
    a0 = d0*d0; a1 = d1*d1;
#pragma unroll
    for (int o = 16; o; o >>= 1){
        a0 += __shfl_down_sync(0xffffffffu, a0, o);
        a1 += __shfl_down_sync(0xffffffffu, a1, o);
    }
    if (lane == 0){ redC[warp] = a0; redD[warp] = a1; }
    __syncthreads();
    if (tid == 0){
        float t0 = 0.f, t1 = 0.f;
#pragma unroll
        for (int i = 0; i < 8; i++){ t0 += redC[i]; t1 += redD[i]; }
        bc[2] = t0 * (1.0f/256.0f); bc[3] = t1 * (1.0f/256.0f);
    }
    __syncthreads();
    float rs0 = rsqrtf(bc[2] + 1e-5f);
    float rs1 = rsqrtf(bc[3] + 1e-5f);

    float gg = lng[tid], bb = lnb[tid];
    float y0 = gelu_exact(d0 * rs0 * gg + bb);
    float y1 = gelu_exact(d1 * rs1 * gg + bb);

    g_H[((size_t)(2*g) + 0) * 256 + tid] = to_tf32(y0);
    g_H[((size_t)(2*g) + 1) * 256 + tid] = to_tf32(y1);

    // ---- dist token row (D=512; 2 cols per thread) ----
    const int bI  = g / (NB_T*NB_NC);
    const int rem = g % (NB_T*NB_NC);
    float* orow = out + ((size_t)bI * 1800 + rem) * 512;
    orow[tid]       = fmaf(dist, dist_w[tid],       dist_b[tid]);
    orow[tid + 256] = fmaf(dist, dist_w[tid + 256], dist_b[tid + 256]);

    // ---- meta ----
    if (tid < 2){
        float* mp = g_meta + ((size_t)(2*g) + tid) * 8;
        mp[0] = scat[tid];
        mp[1] = sconf[tid];
        mp[2] = cxs[tid];
        mp[3] = cys[tid];
        mp[4] = spres[tid];
    }
}

// ---------------------------------------------------------------------------
// Kernel 2: H[153600,256] @ W2[256,512] with tf32 mma.sync, fused epilogue.
// CTA tile 128x128, BK=16, 8 warps (4M x 2N), warp tile 32x64.
// ---------------------------------------------------------------------------
__device__ __forceinline__ void mma_tf32(float* d, const uint32_t* a, const uint32_t* b){
    asm volatile(
        "mma.sync.aligned.m16n8k8.row.col.f32.tf32.tf32.f32 "
        "{%0,%1,%2,%3}, {%4,%5,%6,%7}, {%8,%9}, {%0,%1,%2,%3};\n"
        : "+f"(d[0]), "+f"(d[1]), "+f"(d[2]), "+f"(d[3])
        : "r"(a[0]), "r"(a[1]), "r"(a[2]), "r"(a[3]), "r"(b[0]), "r"(b[1]));
}

__global__ __launch_bounds__(256) void k_gemm(
    const float* __restrict__ W2,  const float* __restrict__ b2,
    const float* __restrict__ conf_w, const float* __restrict__ conf_b,
    const float* __restrict__ center_w, const float* __restrict__ center_b,
    const float* __restrict__ missing,
    const float* __restrict__ cat_table, const float* __restrict__ cam_table,
    const float* __restrict__ scalep,
    float* __restrict__ out)
{
    __shared__ float As[128*20];    // A tile, row stride 20 (conflict-free frags)
    __shared__ float Bs[16*136];    // B tile, row stride 136
    __shared__ float s_base9[9*128];
    __shared__ float s_cw[128], s_c0[128], s_c1[128], s_miss[128];

    const int tid  = threadIdx.x;
    const int lane = tid & 31;
    const int warp = tid >> 5;
    const int wm   = warp & 3;      // 4 warps along M (32 rows each)
    const int wn   = warp >> 2;     // 2 warps along N (64 cols each)
    const int gid  = lane >> 2;     // groupID
    const int tig  = lane & 3;      // thread-in-group

    const int n0 = blockIdx.x * 128;
    const int m0 = blockIdx.y * 128;

    // ---- epilogue tables (cat x cam combined bias, per-col vectors) ----
    for (int i = tid; i < 9*128; i += 256){
        int cc = i >> 7, dl = i & 127, d = n0 + dl;
        int cat = cc / 3, cam = cc % 3;
        s_base9[i] = b2[d] + conf_b[d] + center_b[d]
                   + cat_table[cat*512 + d] + cam_table[cam*512 + d];
    }
    if (tid < 128){
        int d = n0 + tid;
        s_cw[tid]   = conf_w[d];
        s_c0[tid]   = center_w[d];
        s_c1[tid]   = center_w[512 + d];
        s_miss[tid] = missing[d];
    }

    float acc[2][8][4];
#pragma unroll
    for (int i = 0; i < 2; i++)
#pragma unroll
        for (int j = 0; j < 8; j++)
#pragma unroll
            for (int k = 0; k < 4; k++) acc[i][j][k] = 0.0f;

    const float* Ap = g_H + (size_t)m0 * 256;
    const float* Bp = W2 + n0;

    for (int ko = 0; ko < 256; ko += 16){
        // load A tile 128x16 (already tf32-rounded)
#pragma unroll
        for (int u = 0; u < 2; u++){
            int idx = tid + u*256;
            int row = idx >> 2, seg = idx & 3;
            float4 v = *reinterpret_cast<const float4*>(Ap + (size_t)row*256 + ko + seg*4);
            float* dst = As + row*20 + seg*4;
            dst[0]=v.x; dst[1]=v.y; dst[2]=v.z; dst[3]=v.w;
        }
        // load B tile 16x128 (round W2 to tf32)
#pragma unroll
        for (int u = 0; u < 2; u++){
            int idx = tid + u*256;
            int row = idx >> 5, seg = idx & 31;
            float4 v = *reinterpret_cast<const float4*>(Bp + (size_t)(ko+row)*512 + seg*4);
            float* dst = Bs + row*136 + seg*4;
            dst[0]=to_tf32(v.x); dst[1]=to_tf32(v.y);
            dst[2]=to_tf32(v.z); dst[3]=to_tf32(v.w);
        }
        __syncthreads();

#pragma unroll
        for (int ks = 0; ks < 2; ks++){
            const int kk = ks * 8;
            uint32_t af[2][4];
#pragma unroll
            for (int mi = 0; mi < 2; mi++){
                int r = wm*32 + mi*16 + gid;
                af[mi][0] = __float_as_uint(As[ r    *20 + kk + tig    ]);
                af[mi][1] = __float_as_uint(As[(r+8) *20 + kk + tig    ]);
                af[mi][2] = __float_as_uint(As[ r    *20 + kk + tig + 4]);
                af[mi][3] = __float_as_uint(As[(r+8) *20 + kk + tig + 4]);
            }
            uint32_t bf[8][2];
#pragma unroll
            for (int ni = 0; ni < 8; ni++){
                int col = wn*64 + ni*8 + gid;
                bf[ni][0] = __float_as_uint(Bs[(kk + tig    )*136 + col]);
                bf[ni][1] = __float_as_uint(Bs[(kk + tig + 4)*136 + col]);
            }
#pragma unroll
            for (int mi = 0; mi < 2; mi++)
#pragma unroll
                for (int ni = 0; ni < 8; ni++)
                    mma_tf32(acc[mi][ni], af[mi], bf[ni]);
        }
        __syncthreads();
    }

    // ---- fused epilogue ----
    const float scaleV = *scalep;
#pragma unroll
    for (int mi = 0; mi < 2; mi++){
#pragma unroll
        for (int half = 0; half < 2; half++){
            int m = m0 + wm*32 + mi*16 + gid + half*8;
            const float* mp = g_meta + (size_t)m * 8;
            float cat  = mp[0], conf = mp[1];
            float cxv  = mp[2], cyv  = mp[3];
            float pres = mp[4];
            int cc  = ((int)cat)*3 + ((m >> 1) % 3);
            int bI  = m / 1200;
            int rem = m % 1200;
            float* orow = out + ((size_t)bI*1800 + 600 + rem) * 512 + n0;
            const float* bsrow = s_base9 + cc*128;
#pragma unroll
            for (int ni = 0; ni < 8; ni++){
#pragma unroll
                for (int q = 0; q < 2; q++){
                    int dl = wn*64 + ni*8 + tig*2 + q;
                    float v = acc[mi][ni][half*2 + q];
                    v = (v + bsrow[dl] + conf*s_cw[dl] + cxv*s_c0[dl] + cyv*s_c1[dl]) * scaleV;
                    if (pres == 0.0f) v = s_miss[dl];
                    orow[dl] = v;
                }
            }
        }
    }
}

// ---------------------------------------------------------------------------
extern "C" void kernel_launch(void* const* d_in, const int* in_sizes, int n_in,
                              void* d_out, int out_size)
{
    const float* box        = (const float*)d_in[0];
    const float* cat_table  = (const float*)d_in[1];
    const float* W1         = (const float*)d_in[2];
    const float* b1         = (const float*)d_in[3];
    const float* lng        = (const float*)d_in[4];
    const float* lnb        = (const float*)d_in[5];
    const float* W2         = (const float*)d_in[6];
    const float* b2         = (const float*)d_in[7];
    const float* conf_w     = (const float*)d_in[8];
    const float* conf_b     = (const float*)d_in[9];
    const float* center_w   = (const float*)d_in[10];
    const float* center_b   = (const float*)d_in[11];
    const float* missing    = (const float*)d_in[12];
    const float* dist_w     = (const float*)d_in[13];
    const float* dist_b     = (const float*)d_in[14];
    const float* cam_table  = (const float*)d_in[15];
    const float* scalep     = (const float*)d_in[16];
    float* out = (float*)d_out;

    k_features<<<NGROUP, 256>>>(box, W1, b1, lng, lnb, dist_w, dist_b, out);
    k_gemm<<<dim3(4, 1200), 256>>>(W2, b2, conf_w, conf_b, center_w, center_b,
                                   missing, cat_table, cam_table, scalep, out);
}

// round 2
// speedup vs baseline: 1.4425x; 1.4425x over previous
#include <cuda_runtime.h>
#include <cstdint>

#define NB_T 200
#define NB_NC 3
#define NGROUP 76800              /* B*T*NC */
#define NBOX   153600
#define KDIM   256
#define NDIM   512

// Scratch
__device__ float g_H[(size_t)NBOX * KDIM];     // tf32-rounded activations
__device__ float g_W2t[KDIM * NDIM];           // tf32-rounded W2
__device__ float g_meta[(size_t)NBOX * 8];

__device__ __forceinline__ float to_tf32(float x){
    uint32_t u; asm("cvt.rna.tf32.f32 %0, %1;" : "=r"(u) : "f"(x));
    return __uint_as_float(u);
}
__device__ __forceinline__ float gelu_exact(float x){
    return 0.5f * x * (1.0f + erff(x * 0.70710678118654752440f));
}

// ---------------------------------------------------------------------------
__global__ __launch_bounds__(256) void k_prep(const float* __restrict__ W2){
    int i = blockIdx.x * 256 + threadIdx.x;
    g_W2t[i] = to_tf32(W2[i]);
}

// ---------------------------------------------------------------------------
// k_features: 2400 blocks x 256 thr. Warp handles 4 full groups (8 boxes).
// Per group: normalize, 2-sort, features, geom@W1 -> LN (warp allreduce) ->
// GELU -> g_H (tf32); dist token row -> out; meta -> g_meta.
// ---------------------------------------------------------------------------
__global__ __launch_bounds__(256) void k_features(
    const float* __restrict__ box,
    const float* __restrict__ W1, const float* __restrict__ b1,
    const float* __restrict__ lng, const float* __restrict__ lnb,
    const float* __restrict__ dist_w, const float* __restrict__ dist_b,
    float* __restrict__ out)
{
    __shared__ float sW1[2560], sb1[256], sg[256], sbb[256], sdw[512], sdb[512];
    const int tid  = threadIdx.x;
    const int lane = tid & 31;
    const int warp = tid >> 5;

    for (int i = tid; i < 2560; i += 256) sW1[i] = W1[i];
    if (tid < 256){ sb1[tid] = b1[tid]; sg[tid] = lng[tid]; sbb[tid] = lnb[tid]; }
    for (int i = tid; i < 512; i += 256){ sdw[i] = dist_w[i]; sdb[i] = dist_b[i]; }
    __syncthreads();

    for (int it = 0; it < 4; it++){
        const int g = blockIdx.x * 32 + warp * 4 + it;

        const float* bd = box + (size_t)g * 12;
        float raw[12];
#pragma unroll
        for (int i = 0; i < 12; i++) raw[i] = __ldg(bd + i);

        float c0[4], c1[4];
        c0[0]=raw[0]/640.0f; c0[1]=raw[1]/400.0f; c0[2]=raw[2]/640.0f; c0[3]=raw[3]/400.0f;
        c1[0]=raw[6]/640.0f; c1[1]=raw[7]/400.0f; c1[2]=raw[8]/640.0f; c1[3]=raw[9]/400.0f;
        float cat0=raw[4], conf0=raw[5], cat1=raw[10], conf1=raw[11];

        float s0 = ((c0[0]+c0[1])+c0[2])+c0[3];
        float s1 = ((c1[0]+c1[1])+c1[2])+c1[3];
        float p0 = (s0 != 0.0f) ? 1.0f : 0.0f;
        float p1 = (s1 != 0.0f) ? 1.0f : 0.0f;
        const bool swp = (cat1 + (1.0f-p1)*1000.0f) < (cat0 + (1.0f-p0)*1000.0f);

        float sc[2][4], scat[2], sconf[2], spres[2];
#pragma unroll
        for (int k = 0; k < 4; k++){
            sc[0][k] = swp ? c1[k] : c0[k];
            sc[1][k] = swp ? c0[k] : c1[k];
        }
        scat[0]=swp?cat1:cat0;   scat[1]=swp?cat0:cat1;
        sconf[0]=swp?conf1:conf0; sconf[1]=swp?conf0:conf1;
        spres[0]=swp?p1:p0;       spres[1]=swp?p0:p1;

        float cxs[2], cys[2];
#pragma unroll
        for (int s = 0; s < 2; s++){
            float x1=sc[s][0], y1=sc[s][1], x2=sc[s][2], y2=sc[s][3];
            float w=x2-x1, h=y2-y1;
            float cx=(x1+x2)*0.5f, cy=(y1+y2)*0.5f;
            cxs[s]=cx; cys[s]=cy;
            float feat[10] = {x1,y1,x2,y2,w,h,cx,cy,w*h,w/(h+1e-6f)};

            float v[8];
#pragma unroll
            for (int j = 0; j < 8; j++){
                int c = lane + 32*j;
                float a = sb1[c];
#pragma unroll
                for (int f = 0; f < 10; f++) a = fmaf(feat[f], sW1[f*256 + c], a);
                v[j] = a;
            }
            float sum = 0.f;
#pragma unroll
            for (int j = 0; j < 8; j++) sum += v[j];
#pragma unroll
            for (int o = 16; o; o >>= 1) sum += __shfl_xor_sync(0xffffffffu, sum, o);
            float mu = sum * (1.0f/256.0f);

            float var = 0.f;
#pragma unroll
            for (int j = 0; j < 8; j++){ v[j] -= mu; var = fmaf(v[j], v[j], var); }
#pragma unroll
            for (int o = 16; o; o >>= 1) var += __shfl_xor_sync(0xffffffffu, var, o);
            float rs = rsqrtf(var * (1.0f/256.0f) + 1e-5f);

            const size_t m = (size_t)(2*g + s);
#pragma unroll
            for (int j = 0; j < 8; j++){
                int c = lane + 32*j;
                float y = gelu_exact(v[j] * rs * sg[c] + sbb[c]);
                g_H[m*256 + c] = to_tf32(y);
            }
        }

        float dx = cxs[0]-cxs[1], dy = cys[0]-cys[1];
        float dist = sqrtf(dx*dx + dy*dy);
        const int bI = g / (NB_T*NB_NC);
        const int rem = g % (NB_T*NB_NC);
        float* orow = out + ((size_t)bI * 1800 + rem) * 512;
#pragma unroll
        for (int j = 0; j < 16; j++){
            int c = lane + 32*j;
            orow[c] = fmaf(dist, sdw[c], sdb[c]);
        }
        if (lane < 2){
            float* mp = g_meta + (size_t)(2*g + lane) * 8;
            mp[0]=scat[lane]; mp[1]=sconf[lane]; mp[2]=cxs[lane];
            mp[3]=cys[lane];  mp[4]=spres[lane];
        }
    }
}

// ---------------------------------------------------------------------------
// k_gemm: H[153600,256] @ W2t[256,512], CTA tile 128x256, warp tile 64x64,
// BK=8, 3-stage cp.async pipeline, fused epilogue.
// ---------------------------------------------------------------------------
#define BK 8
#define AST 12                 /* A smem row stride (floats) */
#define A_SZ (128*AST)         /* 1536 */
#define B_SZ (BK*256)          /* 2048 */
#define STG_SZ (A_SZ + B_SZ)   /* 3584 floats = 14336 B */

__device__ __forceinline__ void mma_tf32(float* d, const uint32_t* a, const uint32_t* b){
    asm volatile(
        "mma.sync.aligned.m16n8k8.row.col.f32.tf32.tf32.f32 "
        "{%0,%1,%2,%3}, {%4,%5,%6,%7}, {%8,%9}, {%0,%1,%2,%3};\n"
        : "+f"(d[0]), "+f"(d[1]), "+f"(d[2]), "+f"(d[3])
        : "r"(a[0]), "r"(a[1]), "r"(a[2]), "r"(a[3]), "r"(b[0]), "r"(b[1]));
}

#define CP16(dst, src) asm volatile("cp.async.cg.shared.global [%0], [%1], 16;\n" :: "r"(dst), "l"(src))
#define CPCOMMIT()     asm volatile("cp.async.commit_group;\n" ::: "memory")
#define CPWAIT1()      asm volatile("cp.async.wait_group 1;\n" ::: "memory")

__global__ __launch_bounds__(256, 1) void k_gemm(
    const float* __restrict__ b2,
    const float* __restrict__ conf_w, const float* __restrict__ conf_b,
    const float* __restrict__ center_w, const float* __restrict__ center_b,
    const float* __restrict__ missing,
    const float* __restrict__ cat_table, const float* __restrict__ cam_table,
    const float* __restrict__ scalep,
    float* __restrict__ out)
{
    __shared__ __align__(16) float smem[3 * STG_SZ];   // 43008 B, aliased by epilogue tables

    const int tid  = threadIdx.x;
    const int lane = tid & 31;
    const int warp = tid >> 5;
    const int wm   = warp & 1;      // 2 warps along M (64 rows)
    const int wn   = warp >> 1;     // 4 warps along N (64 cols)
    const int gid  = lane >> 2;
    const int tig  = lane & 3;

    const int n0 = blockIdx.x * 256;
    const int m0 = blockIdx.y * 128;

    // stage loader
    const int a_row = tid >> 1, a_half = tid & 1;
    const float* a_src0 = g_H + (size_t)(m0 + a_row) * 256 + a_half * 4;

    auto load_stage = [&](int s, int ko){
        float* As = smem + s * STG_SZ;
        float* Bs = As + A_SZ;
        {
            uint32_t dst = (uint32_t)__cvta_generic_to_shared(As + a_row*AST + a_half*4);
            CP16(dst, a_src0 + ko);
        }
#pragma unroll
        for (int u = 0; u < 2; u++){
            int idx = tid + u*256;
            int row = idx >> 6, c4 = idx & 63;
            int col = c4 * 4;
            int csw = col ^ (8 * (row & 3));
            const float* src = g_W2t + (size_t)(ko + row) * 512 + n0 + col;
            uint32_t dst = (uint32_t)__cvta_generic_to_shared(Bs + row*256 + csw);
            CP16(dst, src);
        }
    };

    float acc[4][8][4];
#pragma unroll
    for (int i = 0; i < 4; i++)
#pragma unroll
        for (int j = 0; j < 8; j++)
#pragma unroll
            for (int k = 0; k < 4; k++) acc[i][j][k] = 0.0f;

    load_stage(0, 0);  CPCOMMIT();
    load_stage(1, BK); CPCOMMIT();

    for (int k = 0; k < 32; k++){
        CPWAIT1();
        __syncthreads();
        if (k + 2 < 32) load_stage((k + 2) % 3, (k + 2) * BK);
        CPCOMMIT();

        const float* As = smem + (k % 3) * STG_SZ;
        const float* Bs = As + A_SZ;

        uint32_t af[4][4];
#pragma unroll
        for (int mi = 0; mi < 4; mi++){
            int r = wm*64 + mi*16 + gid;
            af[mi][0] = __float_as_uint(As[ r    *AST + tig    ]);
            af[mi][1] = __float_as_uint(As[(r+8) *AST + tig    ]);
            af[mi][2] = __float_as_uint(As[ r    *AST + tig + 4]);
            af[mi][3] = __float_as_uint(As[(r+8) *AST + tig + 4]);
        }
        uint32_t bf[8][2];
#pragma unroll
        for (int ni = 0; ni < 8; ni++){
            int colb = (wn*64 + ni*8 + gid) ^ (8*tig);
            bf[ni][0] = __float_as_uint(Bs[ tig   *256 + colb]);
            bf[ni][1] = __float_as_uint(Bs[(tig+4)*256 + colb]);
        }
#pragma unroll
        for (int mi = 0; mi < 4; mi++)
#pragma unroll
            for (int ni = 0; ni < 8; ni++)
                mma_tf32(acc[mi][ni], af[mi], bf[ni]);
    }

    // ---- epilogue tables (alias pipeline smem) ----
    __syncthreads();
    float* s_base9 = smem;            // 9*256
    float* s_cw    = smem + 2304;     // 256
    float* s_c0    = smem + 2560;
    float* s_c1    = smem + 2816;
    float* s_miss  = smem + 3072;
    for (int i = tid; i < 9*256; i += 256){
        int cc = i >> 8, dl = i & 255, d = n0 + dl;
        int cat = cc / 3, cam = cc % 3;
        s_base9[i] = b2[d] + conf_b[d] + center_b[d]
                   + cat_table[cat*512 + d] + cam_table[cam*512 + d];
    }
    {
        int d = n0 + tid;
        s_cw[tid]   = conf_w[d];
        s_c0[tid]   = center_w[d];
        s_c1[tid]   = center_w[512 + d];
        s_miss[tid] = missing[d];
    }
    __syncthreads();

    const float scaleV = *scalep;
#pragma unroll
    for (int mi = 0; mi < 4; mi++){
#pragma unroll
        for (int h = 0; h < 2; h++){
            int m = m0 + wm*64 + mi*16 + gid + h*8;
            const float* mp = g_meta + (size_t)m * 8;
            float cat = mp[0], conf = mp[1], cxv = mp[2], cyv = mp[3], pres = mp[4];
            int cc  = ((int)cat)*3 + ((m >> 1) % 3);
            int bI  = m / 1200;
            int rem = m % 1200;
            float* orow = out + ((size_t)bI*1800 + 600 + rem) * 512 + n0;
            const float* bsr = s_base9 + cc*256;
#pragma unroll
            for (int ni = 0; ni < 8; ni++){
                int dl = wn*64 + ni*8 + tig*2;
                float v0 = acc[mi][ni][h*2 + 0];
                float v1 = acc[mi][ni][h*2 + 1];
                v0 = (v0 + bsr[dl]   + conf*s_cw[dl]   + cxv*s_c0[dl]   + cyv*s_c1[dl])   * scaleV;
                v1 = (v1 + bsr[dl+1] + conf*s_cw[dl+1] + cxv*s_c0[dl+1] + cyv*s_c1[dl+1]) * scaleV;
                if (pres == 0.0f){ v0 = s_miss[dl]; v1 = s_miss[dl+1]; }
                float2 w2; w2.x = v0; w2.y = v1;
                *reinterpret_cast<float2*>(orow + dl) = w2;
            }
        }
    }
}

// ---------------------------------------------------------------------------
extern "C" void kernel_launch(void* const* d_in, const int* in_sizes, int n_in,
                              void* d_out, int out_size)
{
    const float* box        = (const float*)d_in[0];
    const float* cat_table  = (const float*)d_in[1];
    const float* W1         = (const float*)d_in[2];
    const float* b1         = (const float*)d_in[3];
    const float* lng        = (const float*)d_in[4];
    const float* lnb        = (const float*)d_in[5];
    const float* W2         = (const float*)d_in[6];
    const float* b2         = (const float*)d_in[7];
    const float* conf_w     = (const float*)d_in[8];
    const float* conf_b     = (const float*)d_in[9];
    const float* center_w   = (const float*)d_in[10];
    const float* center_b   = (const float*)d_in[11];
    const float* missing    = (const float*)d_in[12];
    const float* dist_w     = (const float*)d_in[13];
    const float* dist_b     = (const float*)d_in[14];
    const float* cam_table  = (const float*)d_in[15];
    const float* scalep     = (const float*)d_in[16];
    float* out = (float*)d_out;

    k_prep<<<512, 256>>>(W2);
    k_features<<<2400, 256>>>(box, W1, b1, lng, lnb, dist_w, dist_b, out);
    k_gemm<<<dim3(2, 1200), 256>>>(b2, conf_w, conf_b, center_w, center_b,
                                   missing, cat_table, cam_table, scalep, out);
}

// round 4
// speedup vs baseline: 1.6403x; 1.1371x over previous
#include <cuda_runtime.h>
#include <cuda_fp16.h>
#include <cstdint>

#define NB_T 200
#define NB_NC 3
#define NGROUP 76800
#define NBOX   153600

// Scratch
__device__ __half g_Hh[(size_t)NBOX * 256];    // activations [M,K] row-major fp16
__device__ __half g_W2h[512 * 256];            // W2 transposed -> [N,K] row-major fp16
__device__ float  g_meta[(size_t)NBOX * 8];

__device__ __forceinline__ float gelu_exact(float x){
    return 0.5f * x * (1.0f + erff(x * 0.70710678118654752440f));
}
__device__ __forceinline__ uint32_t smem_u32(const void* p){
    return (uint32_t)__cvta_generic_to_shared(p);
}

#define CP16(dst, src) asm volatile("cp.async.cg.shared.global [%0], [%1], 16;\n" :: "r"(dst), "l"(src))
#define CPCOMMIT()     asm volatile("cp.async.commit_group;\n" ::: "memory")
#define CPWAIT1()      asm volatile("cp.async.wait_group 1;\n" ::: "memory")

// ---------------------------------------------------------------------------
// k_prep: W2[K=256,N=512] row-major -> g_W2h[N,K] fp16
// ---------------------------------------------------------------------------
__global__ __launch_bounds__(256) void k_prep(const float* __restrict__ W2){
    int idx = blockIdx.x * 256 + threadIdx.x;   // 131072
    int k = idx >> 9, n = idx & 511;
    g_W2h[n * 256 + k] = __float2half(W2[idx]);
}

// ---------------------------------------------------------------------------
// k_features: warp handles 4 groups; LN via warp allreduce; H -> fp16.
// ---------------------------------------------------------------------------
__global__ __launch_bounds__(256) void k_features(
    const float* __restrict__ box,
    const float* __restrict__ W1, const float* __restrict__ b1,
    const float* __restrict__ lng, const float* __restrict__ lnb,
    const float* __restrict__ dist_w, const float* __restrict__ dist_b,
    float* __restrict__ out)
{
    __shared__ float sW1[2560], sb1[256], sg[256], sbb[256], sdw[512], sdb[512];
    const int tid  = threadIdx.x;
    const int lane = tid & 31;
    const int warp = tid >> 5;

    for (int i = tid; i < 2560; i += 256) sW1[i] = W1[i];
    if (tid < 256){ sb1[tid] = b1[tid]; sg[tid] = lng[tid]; sbb[tid] = lnb[tid]; }
    for (int i = tid; i < 512; i += 256){ sdw[i] = dist_w[i]; sdb[i] = dist_b[i]; }
    __syncthreads();

    for (int it = 0; it < 4; it++){
        const int g = blockIdx.x * 32 + warp * 4 + it;

        const float4* bd4 = (const float4*)(box + (size_t)g * 12);
        float4 rA = __ldg(bd4), rB = __ldg(bd4+1), rC = __ldg(bd4+2);

        float c0[4], c1[4];
        c0[0]=rA.x/640.0f; c0[1]=rA.y/400.0f; c0[2]=rA.z/640.0f; c0[3]=rA.w/400.0f;
        c1[0]=rB.z/640.0f; c1[1]=rB.w/400.0f; c1[2]=rC.x/640.0f; c1[3]=rC.y/400.0f;
        float cat0=rB.x, conf0=rB.y, cat1=rC.z, conf1=rC.w;

        float s0 = ((c0[0]+c0[1])+c0[2])+c0[3];
        float s1 = ((c1[0]+c1[1])+c1[2])+c1[3];
        float p0 = (s0 != 0.0f) ? 1.0f : 0.0f;
        float p1 = (s1 != 0.0f) ? 1.0f : 0.0f;
        const bool swp = (cat1 + (1.0f-p1)*1000.0f) < (cat0 + (1.0f-p0)*1000.0f);

        float sc[2][4], scat[2], sconf[2], spres[2];
#pragma unroll
        for (int k = 0; k < 4; k++){
            sc[0][k] = swp ? c1[k] : c0[k];
            sc[1][k] = swp ? c0[k] : c1[k];
        }
        scat[0]=swp?cat1:cat0;   scat[1]=swp?cat0:cat1;
        sconf[0]=swp?conf1:conf0; sconf[1]=swp?conf0:conf1;
        spres[0]=swp?p1:p0;       spres[1]=swp?p0:p1;

        float cxs[2], cys[2];
#pragma unroll
        for (int s = 0; s < 2; s++){
            float x1=sc[s][0], y1=sc[s][1], x2=sc[s][2], y2=sc[s][3];
            float w=x2-x1, h=y2-y1;
            float cx=(x1+x2)*0.5f, cy=(y1+y2)*0.5f;
            cxs[s]=cx; cys[s]=cy;
            float feat[10] = {x1,y1,x2,y2,w,h,cx,cy,w*h,w/(h+1e-6f)};

            float v[8];
#pragma unroll
            for (int j = 0; j < 8; j++){
                int c = lane + 32*j;
                float a = sb1[c];
#pragma unroll
                for (int f = 0; f < 10; f++) a = fmaf(feat[f], sW1[f*256 + c], a);
                v[j] = a;
            }
            float sum = 0.f;
#pragma unroll
            for (int j = 0; j < 8; j++) sum += v[j];
#pragma unroll
            for (int o = 16; o; o >>= 1) sum += __shfl_xor_sync(0xffffffffu, sum, o);
            float mu = sum * (1.0f/256.0f);

            float var = 0.f;
#pragma unroll
            for (int j = 0; j < 8; j++){ v[j] -= mu; var = fmaf(v[j], v[j], var); }
#pragma unroll
            for (int o = 16; o; o >>= 1) var += __shfl_xor_sync(0xffffffffu, var, o);
            float rs = rsqrtf(var * (1.0f/256.0f) + 1e-5f);

            const size_t m = (size_t)(2*g + s);
#pragma unroll
            for (int j = 0; j < 8; j++){
                int c = lane + 32*j;
                float y = gelu_exact(v[j] * rs * sg[c] + sbb[c]);
                g_Hh[m*256 + c] = __float2half(y);
            }
        }

        float dx = cxs[0]-cxs[1], dy = cys[0]-cys[1];
        float dist = sqrtf(dx*dx + dy*dy);
        const int bI = g / (NB_T*NB_NC);
        const int rem = g % (NB_T*NB_NC);
        float* orow = out + ((size_t)bI * 1800 + rem) * 512;
#pragma unroll
        for (int j = 0; j < 16; j++){
            int c = lane + 32*j;
            orow[c] = fmaf(dist, sdw[c], sdb[c]);
        }
        if (lane < 2){
            float* mp = g_meta + (size_t)(2*g + lane) * 8;
            mp[0]=scat[lane]; mp[1]=sconf[lane]; mp[2]=cxs[lane];
            mp[3]=cys[lane];  mp[4]=spres[lane];
        }
    }
}

// ---------------------------------------------------------------------------
// k_gemm: fp16 mma.sync m16n8k16. CTA tile 128x256, warp tile 64x64, BK=32,
// 3-stage cp.async pipeline, fused epilogue. A/B smem rows padded to 40 halves
// (80B) -> conflict-free 32-bit frag loads.
// ---------------------------------------------------------------------------
#define BK 32
#define RST 40                         /* row stride in halves */
#define A_HALVES (128*RST)             /* 5120 */
#define B_HALVES (256*RST)             /* 10240 */
#define STG_HALVES (A_HALVES + B_HALVES)   /* 15360 halves = 30720 B */

__device__ __forceinline__ void mma_f16(float* d, const uint32_t* a, const uint32_t* b){
    asm volatile(
        "mma.sync.aligned.m16n8k16.row.col.f32.f16.f16.f32 "
        "{%0,%1,%2,%3}, {%4,%5,%6,%7}, {%8,%9}, {%0,%1,%2,%3};\n"
        : "+f"(d[0]), "+f"(d[1]), "+f"(d[2]), "+f"(d[3])
        : "r"(a[0]), "r"(a[1]), "r"(a[2]), "r"(a[3]), "r"(b[0]), "r"(b[1]));
}

__global__ __launch_bounds__(256, 1) void k_gemm(
    const float* __restrict__ b2,
    const float* __restrict__ conf_w, const float* __restrict__ conf_b,
    const float* __restrict__ center_w, const float* __restrict__ center_b,
    const float* __restrict__ missing,
    const float* __restrict__ cat_table, const float* __restrict__ cam_table,
    const float* __restrict__ scalep,
    float* __restrict__ out)
{
    extern __shared__ __align__(16) __half sm[];   // 3 stages

    const int tid  = threadIdx.x;
    const int lane = tid & 31;
    const int warp = tid >> 5;
    const int wm   = warp & 1;      // 2 warps along M (64 rows)
    const int wn   = warp >> 1;     // 4 warps along N (64 cols)
    const int gid  = lane >> 2;
    const int tig  = lane & 3;

    const int n0 = blockIdx.x * 256;
    const int m0 = blockIdx.y * 128;

    auto load_stage = [&](int s, int ko){
        __half* As = sm + s * STG_HALVES;
        __half* Bs = As + A_HALVES;
        uint32_t ab = smem_u32(As), bb = smem_u32(Bs);
#pragma unroll
        for (int u = 0; u < 2; u++){                 // A: 512 x 16B chunks
            int c = tid + u*256;
            int row = c >> 2, seg = c & 3;
            const __half* src = g_Hh + (size_t)(m0 + row) * 256 + ko + seg*8;
            CP16(ab + row*80 + seg*16, src);
        }
#pragma unroll
        for (int u = 0; u < 4; u++){                 // B: 1024 x 16B chunks
            int c = tid + u*256;
            int n = c >> 2, seg = c & 3;
            const __half* src = g_W2h + (size_t)(n0 + n) * 256 + ko + seg*8;
            CP16(bb + n*80 + seg*16, src);
        }
    };

    float acc[4][8][4];
#pragma unroll
    for (int i = 0; i < 4; i++)
#pragma unroll
        for (int j = 0; j < 8; j++)
#pragma unroll
            for (int k = 0; k < 4; k++) acc[i][j][k] = 0.0f;

    load_stage(0, 0);  CPCOMMIT();
    load_stage(1, BK); CPCOMMIT();

    for (int k = 0; k < 8; k++){
        CPWAIT1();
        __syncthreads();
        if (k + 2 < 8) load_stage((k + 2) % 3, (k + 2) * BK);
        CPCOMMIT();

        const __half* As = sm + (k % 3) * STG_HALVES;
        const __half* Bs = As + A_HALVES;

#pragma unroll
        for (int ks = 0; ks < 2; ks++){
            const int kk = ks * 16;
            uint32_t af[4][4];
#pragma unroll
            for (int mi = 0; mi < 4; mi++){
                int r = wm*64 + mi*16 + gid;
                af[mi][0] = *(const uint32_t*)&As[ r    *RST + kk + tig*2    ];
                af[mi][1] = *(const uint32_t*)&As[(r+8) *RST + kk + tig*2    ];
                af[mi][2] = *(const uint32_t*)&As[ r    *RST + kk + tig*2 + 8];
                af[mi][3] = *(const uint32_t*)&As[(r+8) *RST + kk + tig*2 + 8];
            }
            uint32_t bf[8][2];
#pragma unroll
            for (int ni = 0; ni < 8; ni++){
                int n = wn*64 + ni*8 + gid;
                bf[ni][0] = *(const uint32_t*)&Bs[n*RST + kk + tig*2    ];
                bf[ni][1] = *(const uint32_t*)&Bs[n*RST + kk + tig*2 + 8];
            }
#pragma unroll
            for (int mi = 0; mi < 4; mi++)
#pragma unroll
                for (int ni = 0; ni < 8; ni++)
                    mma_f16(acc[mi][ni], af[mi], bf[ni]);
        }
        __syncthreads();
    }

    // ---- epilogue tables (alias pipeline smem) ----
    float* s_base9 = (float*)sm;          // 9*256
    float* s_cw    = s_base9 + 9*256;     // 256 each
    float* s_c0    = s_cw + 256;
    float* s_c1    = s_c0 + 256;
    float* s_miss  = s_c1 + 256;
    for (int i = tid; i < 9*256; i += 256){
        int cc = i >> 8, dl = i & 255, d = n0 + dl;
        s_base9[i] = b2[d] + conf_b[d] + center_b[d]
                   + cat_table[(cc/3)*512 + d] + cam_table[(cc%3)*512 + d];
    }
    {
        int d = n0 + tid;
        s_cw[tid]   = conf_w[d];
        s_c0[tid]   = center_w[d];
        s_c1[tid]   = center_w[512 + d];
        s_miss[tid] = missing[d];
    }
    __syncthreads();

    const float scaleV = *scalep;
#pragma unroll
    for (int mi = 0; mi < 4; mi++){
#pragma unroll
        for (int h = 0; h < 2; h++){
            int m = m0 + wm*64 + mi*16 + gid + h*8;
            const float* mp = g_meta + (size_t)m * 8;
            float cat = mp[0], conf = mp[1], cxv = mp[2], cyv = mp[3], pres = mp[4];
            int cc  = ((int)cat)*3 + ((m >> 1) % 3);
            int bI  = m / 1200;
            int rem = m % 1200;
            float* orow = out + ((size_t)bI*1800 + 600 + rem) * 512 + n0;
            const float* bsr = s_base9 + cc*256;
#pragma unroll
            for (int ni = 0; ni < 8; ni++){
                int dl = wn*64 + ni*8 + tig*2;
                float v0 = acc[mi][ni][h*2 + 0];
                float v1 = acc[mi][ni][h*2 + 1];
                v0 = (v0 + bsr[dl]   + conf*s_cw[dl]   + cxv*s_c0[dl]   + cyv*s_c1[dl])   * scaleV;
                v1 = (v1 + bsr[dl+1] + conf*s_cw[dl+1] + cxv*s_c0[dl+1] + cyv*s_c1[dl+1]) * scaleV;
                if (pres == 0.0f){ v0 = s_miss[dl]; v1 = s_miss[dl+1]; }
                float2 w2; w2.x = v0; w2.y = v1;
                *reinterpret_cast<float2*>(orow + dl) = w2;
            }
        }
    }
}

// ---------------------------------------------------------------------------
extern "C" void kernel_launch(void* const* d_in, const int* in_sizes, int n_in,
                              void* d_out, int out_size)
{
    const float* box        = (const float*)d_in[0];
    const float* cat_table  = (const float*)d_in[1];
    const float* W1         = (const float*)d_in[2];
    const float* b1         = (const float*)d_in[3];
    const float* lng        = (const float*)d_in[4];
    const float* lnb        = (const float*)d_in[5];
    const float* W2         = (const float*)d_in[6];
    const float* b2         = (const float*)d_in[7];
    const float* conf_w     = (const float*)d_in[8];
    const float* conf_b     = (const float*)d_in[9];
    const float* center_w   = (const float*)d_in[10];
    const float* center_b   = (const float*)d_in[11];
    const float* missing    = (const float*)d_in[12];
    const float* dist_w     = (const float*)d_in[13];
    const float* dist_b     = (const float*)d_in[14];
    const float* cam_table  = (const float*)d_in[15];
    const float* scalep     = (const float*)d_in[16];
    float* out = (float*)d_out;

    const int dyn_smem = 3 * STG_HALVES * 2;   // 92160 B
    cudaFuncSetAttribute(k_gemm, cudaFuncAttributeMaxDynamicSharedMemorySize, dyn_smem);

    k_prep<<<512, 256>>>(W2);
    k_features<<<2400, 256>>>(box, W1, b1, lng, lnb, dist_w, dist_b, out);
    k_gemm<<<dim3(2, 1200), 256, dyn_smem>>>(b2, conf_w, conf_b, center_w, center_b,
                                             missing, cat_table, cam_table, scalep, out);
}

// round 5
// speedup vs baseline: 1.7511x; 1.0676x over previous
#include <cuda_runtime.h>
#include <cuda_fp16.h>
#include <cstdint>

#define NB_T 200
#define NB_NC 3
#define NGROUP 76800
#define NBOX   153600

// Scratch
__device__ __half g_Hh[(size_t)NBOX * 256];    // activations [M,K] row-major fp16
__device__ __half g_W2h[512 * 256];            // W2 transposed -> [N,K] row-major fp16
__device__ float  g_meta[(size_t)NBOX * 8];

__device__ __forceinline__ float gelu_exact(float x){
    return 0.5f * x * (1.0f + erff(x * 0.70710678118654752440f));
}
__device__ __forceinline__ uint32_t smem_u32(const void* p){
    return (uint32_t)__cvta_generic_to_shared(p);
}

#define CP16(dst, src) asm volatile("cp.async.cg.shared.global [%0], [%1], 16;\n" :: "r"(dst), "l"(src))
#define CPCOMMIT()     asm volatile("cp.async.commit_group;\n" ::: "memory")
#define CPWAIT1()      asm volatile("cp.async.wait_group 1;\n" ::: "memory")

__device__ __forceinline__ void ldsm_x4(uint32_t* r, uint32_t addr){
    asm volatile("ldmatrix.sync.aligned.m8n8.x4.shared.b16 {%0,%1,%2,%3}, [%4];\n"
        : "=r"(r[0]), "=r"(r[1]), "=r"(r[2]), "=r"(r[3]) : "r"(addr));
}

// ---------------------------------------------------------------------------
// k_features: warp handles 4 groups; LN via warp allreduce; H -> fp16.
// Blocks < 512 additionally transpose W2 -> g_W2h (fp16), replacing k_prep.
// ---------------------------------------------------------------------------
__global__ __launch_bounds__(256) void k_features(
    const float* __restrict__ box,
    const float* __restrict__ W1, const float* __restrict__ b1,
    const float* __restrict__ lng, const float* __restrict__ lnb,
    const float* __restrict__ dist_w, const float* __restrict__ dist_b,
    const float* __restrict__ W2,
    float* __restrict__ out)
{
    __shared__ float sW1[2560], sb1[256], sg[256], sbb[256], sdw[512], sdb[512];
    const int tid  = threadIdx.x;
    const int lane = tid & 31;
    const int warp = tid >> 5;

    if (blockIdx.x < 512){                       // merged k_prep
        int idx = blockIdx.x * 256 + tid;
        int k = idx >> 9, n = idx & 511;
        g_W2h[n * 256 + k] = __float2half(W2[idx]);
    }

    for (int i = tid; i < 2560; i += 256) sW1[i] = W1[i];
    if (tid < 256){ sb1[tid] = b1[tid]; sg[tid] = lng[tid]; sbb[tid] = lnb[tid]; }
    for (int i = tid; i < 512; i += 256){ sdw[i] = dist_w[i]; sdb[i] = dist_b[i]; }
    __syncthreads();

    for (int it = 0; it < 4; it++){
        const int g = blockIdx.x * 32 + warp * 4 + it;

        const float4* bd4 = (const float4*)(box + (size_t)g * 12);
        float4 rA = __ldg(bd4), rB = __ldg(bd4+1), rC = __ldg(bd4+2);

        float c0[4], c1[4];
        c0[0]=rA.x/640.0f; c0[1]=rA.y/400.0f; c0[2]=rA.z/640.0f; c0[3]=rA.w/400.0f;
        c1[0]=rB.z/640.0f; c1[1]=rB.w/400.0f; c1[2]=rC.x/640.0f; c1[3]=rC.y/400.0f;
        float cat0=rB.x, conf0=rB.y, cat1=rC.z, conf1=rC.w;

        float s0 = ((c0[0]+c0[1])+c0[2])+c0[3];
        float s1 = ((c1[0]+c1[1])+c1[2])+c1[3];
        float p0 = (s0 != 0.0f) ? 1.0f : 0.0f;
        float p1 = (s1 != 0.0f) ? 1.0f : 0.0f;
        const bool swp = (cat1 + (1.0f-p1)*1000.0f) < (cat0 + (1.0f-p0)*1000.0f);

        float sc[2][4], scat[2], sconf[2], spres[2];
#pragma unroll
        for (int k = 0; k < 4; k++){
            sc[0][k] = swp ? c1[k] : c0[k];
            sc[1][k] = swp ? c0[k] : c1[k];
        }
        scat[0]=swp?cat1:cat0;   scat[1]=swp?cat0:cat1;
        sconf[0]=swp?conf1:conf0; sconf[1]=swp?conf0:conf1;
        spres[0]=swp?p1:p0;       spres[1]=swp?p0:p1;

        float cxs[2], cys[2];
#pragma unroll
        for (int s = 0; s < 2; s++){
            float x1=sc[s][0], y1=sc[s][1], x2=sc[s][2], y2=sc[s][3];
            float w=x2-x1, h=y2-y1;
            float cx=(x1+x2)*0.5f, cy=(y1+y2)*0.5f;
            cxs[s]=cx; cys[s]=cy;
            float feat[10] = {x1,y1,x2,y2,w,h,cx,cy,w*h,w/(h+1e-6f)};

            float v[8];
#pragma unroll
            for (int j = 0; j < 8; j++){
                int c = lane + 32*j;
                float a = sb1[c];
#pragma unroll
                for (int f = 0; f < 10; f++) a = fmaf(feat[f], sW1[f*256 + c], a);
                v[j] = a;
            }
            float sum = 0.f;
#pragma unroll
            for (int j = 0; j < 8; j++) sum += v[j];
#pragma unroll
            for (int o = 16; o; o >>= 1) sum += __shfl_xor_sync(0xffffffffu, sum, o);
            float mu = sum * (1.0f/256.0f);

            float var = 0.f;
#pragma unroll
            for (int j = 0; j < 8; j++){ v[j] -= mu; var = fmaf(v[j], v[j], var); }
#pragma unroll
            for (int o = 16; o; o >>= 1) var += __shfl_xor_sync(0xffffffffu, var, o);
            float rs = rsqrtf(var * (1.0f/256.0f) + 1e-5f);

            const size_t m = (size_t)(2*g + s);
#pragma unroll
            for (int j = 0; j < 8; j++){
                int c = lane + 32*j;
                float y = gelu_exact(v[j] * rs * sg[c] + sbb[c]);
                g_Hh[m*256 + c] = __float2half(y);
            }
        }

        float dx = cxs[0]-cxs[1], dy = cys[0]-cys[1];
        float dist = sqrtf(dx*dx + dy*dy);
        const int bI = g / (NB_T*NB_NC);
        const int rem = g % (NB_T*NB_NC);
        float* orow = out + ((size_t)bI * 1800 + rem) * 512;
#pragma unroll
        for (int j = 0; j < 16; j++){
            int c = lane + 32*j;
            orow[c] = fmaf(dist, sdw[c], sdb[c]);
        }
        if (lane < 2){
            float* mp = g_meta + (size_t)(2*g + lane) * 8;
            mp[0]=scat[lane]; mp[1]=sconf[lane]; mp[2]=cxs[lane];
            mp[3]=cys[lane];  mp[4]=spres[lane];
        }
    }
}

// ---------------------------------------------------------------------------
// k_gemm: fp16 mma.sync m16n8k16 with ldmatrix.x4 frag loads.
// CTA tile 128x256, warp tile 64x64, BK=32, 3-stage cp.async, fused epilogue.
// ---------------------------------------------------------------------------
#define BK 32
#define RST 40                         /* row stride in halves (80 B) */
#define A_HALVES (128*RST)
#define B_HALVES (256*RST)
#define STG_HALVES (A_HALVES + B_HALVES)

__device__ __forceinline__ void mma_f16(float* d, const uint32_t* a, const uint32_t* b){
    asm volatile(
        "mma.sync.aligned.m16n8k16.row.col.f32.f16.f16.f32 "
        "{%0,%1,%2,%3}, {%4,%5,%6,%7}, {%8,%9}, {%0,%1,%2,%3};\n"
        : "+f"(d[0]), "+f"(d[1]), "+f"(d[2]), "+f"(d[3])
        : "r"(a[0]), "r"(a[1]), "r"(a[2]), "r"(a[3]), "r"(b[0]), "r"(b[1]));
}

__global__ __launch_bounds__(256, 1) void k_gemm(
    const float* __restrict__ b2,
    const float* __restrict__ conf_w, const float* __restrict__ conf_b,
    const float* __restrict__ center_w, const float* __restrict__ center_b,
    const float* __restrict__ missing,
    const float* __restrict__ cat_table, const float* __restrict__ cam_table,
    const float* __restrict__ scalep,
    float* __restrict__ out)
{
    extern __shared__ __align__(16) __half sm[];   // 3 stages

    const int tid  = threadIdx.x;
    const int lane = tid & 31;
    const int warp = tid >> 5;
    const int wm   = warp & 1;      // 2 warps along M (64 rows)
    const int wn   = warp >> 1;     // 4 warps along N (64 cols)
    const int gid  = lane >> 2;
    const int tig  = lane & 3;

    const int n0 = blockIdx.x * 256;
    const int m0 = blockIdx.y * 128;

    // ldmatrix per-lane row/col selects
    const int a_row_sel = (lane & 7) + ((lane >> 3) & 1) * 8;   // +8 on lane bit3
    const int a_col_sel = ((lane >> 4) & 1) * 8;                // +8 on lane bit4
    const int b_row_sel = (lane & 7) + ((lane >> 4) & 1) * 8;   // +8 on lane bit4
    const int b_col_sel = ((lane >> 3) & 1) * 8;                // +8 on lane bit3

    auto load_stage = [&](int s, int ko){
        __half* As = sm + s * STG_HALVES;
        __half* Bs = As + A_HALVES;
        uint32_t ab = smem_u32(As), bb = smem_u32(Bs);
#pragma unroll
        for (int u = 0; u < 2; u++){                 // A: 512 x 16B chunks
            int c = tid + u*256;
            int row = c >> 2, seg = c & 3;
            const __half* src = g_Hh + (size_t)(m0 + row) * 256 + ko + seg*8;
            CP16(ab + row*80 + seg*16, src);
        }
#pragma unroll
        for (int u = 0; u < 4; u++){                 // B: 1024 x 16B chunks
            int c = tid + u*256;
            int n = c >> 2, seg = c & 3;
            const __half* src = g_W2h + (size_t)(n0 + n) * 256 + ko + seg*8;
            CP16(bb + n*80 + seg*16, src);
        }
    };

    float acc[4][8][4];
#pragma unroll
    for (int i = 0; i < 4; i++)
#pragma unroll
        for (int j = 0; j < 8; j++)
#pragma unroll
            for (int k = 0; k < 4; k++) acc[i][j][k] = 0.0f;

    load_stage(0, 0);  CPCOMMIT();
    load_stage(1, BK); CPCOMMIT();

    for (int k = 0; k < 8; k++){
        CPWAIT1();
        __syncthreads();
        if (k + 2 < 8) load_stage((k + 2) % 3, (k + 2) * BK);
        CPCOMMIT();

        const __half* As = sm + (k % 3) * STG_HALVES;
        const __half* Bs = As + A_HALVES;
        const uint32_t a32 = smem_u32(As);
        const uint32_t b32 = smem_u32(Bs);

#pragma unroll
        for (int ks = 0; ks < 2; ks++){
            const int kk = ks * 16;
            uint32_t af[4][4];
#pragma unroll
            for (int mi = 0; mi < 4; mi++){
                int row = wm*64 + mi*16 + a_row_sel;
                ldsm_x4(af[mi], a32 + (row*RST + kk + a_col_sel)*2);
            }
            uint32_t bf[8][2];
#pragma unroll
            for (int nio = 0; nio < 4; nio++){
                uint32_t r[4];
                int row = wn*64 + nio*16 + b_row_sel;
                ldsm_x4(r, b32 + (row*RST + kk + b_col_sel)*2);
                bf[nio*2  ][0] = r[0]; bf[nio*2  ][1] = r[1];
                bf[nio*2+1][0] = r[2]; bf[nio*2+1][1] = r[3];
            }
#pragma unroll
            for (int mi = 0; mi < 4; mi++)
#pragma unroll
                for (int ni = 0; ni < 8; ni++)
                    mma_f16(acc[mi][ni], af[mi], bf[ni]);
        }
        __syncthreads();
    }

    // ---- epilogue tables (alias pipeline smem) ----
    float* s_base9 = (float*)sm;          // 9*256
    float* s_cw    = s_base9 + 9*256;     // 256 each
    float* s_c0    = s_cw + 256;
    float* s_c1    = s_c0 + 256;
    float* s_miss  = s_c1 + 256;
    for (int i = tid; i < 9*256; i += 256){
        int cc = i >> 8, dl = i & 255, d = n0 + dl;
        s_base9[i] = b2[d] + conf_b[d] + center_b[d]
                   + cat_table[(cc/3)*512 + d] + cam_table[(cc%3)*512 + d];
    }
    {
        int d = n0 + tid;
        s_cw[tid]   = conf_w[d];
        s_c0[tid]   = center_w[d];
        s_c1[tid]   = center_w[512 + d];
        s_miss[tid] = missing[d];
    }
    __syncthreads();

    const float scaleV = *scalep;
#pragma unroll
    for (int mi = 0; mi < 4; mi++){
#pragma unroll
        for (int h = 0; h < 2; h++){
            int m = m0 + wm*64 + mi*16 + gid + h*8;
            const float* mp = g_meta + (size_t)m * 8;
            float cat = mp[0], conf = mp[1], cxv = mp[2], cyv = mp[3], pres = mp[4];
            int cc  = ((int)cat)*3 + ((m >> 1) % 3);
            int bI  = m / 1200;
            int rem = m % 1200;
            float* orow = out + ((size_t)bI*1800 + 600 + rem) * 512 + n0;
            const float* bsr = s_base9 + cc*256;
#pragma unroll
            for (int ni = 0; ni < 8; ni++){
                int dl = wn*64 + ni*8 + tig*2;
                float v0 = acc[mi][ni][h*2 + 0];
                float v1 = acc[mi][ni][h*2 + 1];
                v0 = (v0 + bsr[dl]   + conf*s_cw[dl]   + cxv*s_c0[dl]   + cyv*s_c1[dl])   * scaleV;
                v1 = (v1 + bsr[dl+1] + conf*s_cw[dl+1] + cxv*s_c0[dl+1] + cyv*s_c1[dl+1]) * scaleV;
                if (pres == 0.0f){ v0 = s_miss[dl]; v1 = s_miss[dl+1]; }
                float2 w2; w2.x = v0; w2.y = v1;
                *reinterpret_cast<float2*>(orow + dl) = w2;
            }
        }
    }
}

// ---------------------------------------------------------------------------
extern "C" void kernel_launch(void* const* d_in, const int* in_sizes, int n_in,
                              void* d_out, int out_size)
{
    const float* box        = (const float*)d_in[0];
    const float* cat_table  = (const float*)d_in[1];
    const float* W1         = (const float*)d_in[2];
    const float* b1         = (const float*)d_in[3];
    const float* lng        = (const float*)d_in[4];
    const float* lnb        = (const float*)d_in[5];
    const float* W2         = (const float*)d_in[6];
    const float* b2         = (const float*)d_in[7];
    const float* conf_w     = (const float*)d_in[8];
    const float* conf_b     = (const float*)d_in[9];
    const float* center_w   = (const float*)d_in[10];
    const float* center_b   = (const float*)d_in[11];
    const float* missing    = (const float*)d_in[12];
    const float* dist_w     = (const float*)d_in[13];
    const float* dist_b     = (const float*)d_in[14];
    const float* cam_table  = (const float*)d_in[15];
    const float* scalep     = (const float*)d_in[16];
    float* out = (float*)d_out;

    const int dyn_smem = 3 * STG_HALVES * 2;   // 92160 B
    cudaFuncSetAttribute(k_gemm, cudaFuncAttributeMaxDynamicSharedMemorySize, dyn_smem);

    k_features<<<2400, 256>>>(box, W1, b1, lng, lnb, dist_w, dist_b, W2, out);
    k_gemm<<<dim3(2, 1200), 256, dyn_smem>>>(b2, conf_w, conf_b, center_w, center_b,
                                             missing, cat_table, cam_table, scalep, out);
}

// round 6
// speedup vs baseline: 1.9301x; 1.1022x over previous
#include <cuda_runtime.h>
#include <cuda_fp16.h>
#include <cstdint>

#define NB_T 200
#define NB_NC 3
#define NGROUP 76800
#define NBOX   153600

// Scratch
__device__ __half g_Hh[(size_t)NBOX * 256];    // activations [M,K] row-major fp16
__device__ __half g_W2h[512 * 256];            // W2 transposed -> [N,K] row-major fp16
__device__ float  g_meta[(size_t)NBOX * 8];

__device__ __forceinline__ float gelu_exact(float x){
    return 0.5f * x * (1.0f + erff(x * 0.70710678118654752440f));
}
__device__ __forceinline__ uint32_t smem_u32(const void* p){
    return (uint32_t)__cvta_generic_to_shared(p);
}

#define CP16(dst, src) asm volatile("cp.async.cg.shared.global [%0], [%1], 16;\n" :: "r"(dst), "l"(src))
#define CPCOMMIT()     asm volatile("cp.async.commit_group;\n" ::: "memory")
#define CPWAIT1()      asm volatile("cp.async.wait_group 1;\n" ::: "memory")

__device__ __forceinline__ void ldsm_x4(uint32_t* r, uint32_t addr){
    asm volatile("ldmatrix.sync.aligned.m8n8.x4.shared.b16 {%0,%1,%2,%3}, [%4];\n"
        : "=r"(r[0]), "=r"(r[1]), "=r"(r[2]), "=r"(r[3]) : "r"(addr));
}

// ---------------------------------------------------------------------------
// k_features: 4800 blocks, warp handles 2 groups. Paired-column mapping:
// lane owns cols {2*lane, 2*lane+1} + 64q  (q=0..3) -> float2 smem loads,
// half2 H stores. Dist row via float4. Blocks < 512 transpose W2.
// ---------------------------------------------------------------------------
__global__ __launch_bounds__(256) void k_features(
    const float* __restrict__ box,
    const float* __restrict__ W1, const float* __restrict__ b1,
    const float* __restrict__ lng, const float* __restrict__ lnb,
    const float* __restrict__ dist_w, const float* __restrict__ dist_b,
    const float* __restrict__ W2,
    float* __restrict__ out)
{
    __shared__ __align__(16) float sW1[2560];
    __shared__ __align__(16) float sb1[256], sg[256], sbb[256];
    __shared__ __align__(16) float sdw[512], sdb[512];
    const int tid  = threadIdx.x;
    const int lane = tid & 31;
    const int warp = tid >> 5;

    if (blockIdx.x < 512){                       // merged W2 transpose
        int idx = blockIdx.x * 256 + tid;
        int k = idx >> 9, n = idx & 511;
        g_W2h[n * 256 + k] = __float2half(W2[idx]);
    }

    for (int i = tid; i < 2560; i += 256) sW1[i] = W1[i];
    if (tid < 256){ sb1[tid] = b1[tid]; sg[tid] = lng[tid]; sbb[tid] = lnb[tid]; }
    for (int i = tid; i < 512; i += 256){ sdw[i] = dist_w[i]; sdb[i] = dist_b[i]; }
    __syncthreads();

    const float2* sW1f2 = (const float2*)sW1;
    const float2* sb1f2 = (const float2*)sb1;
    const float2* sgf2  = (const float2*)sg;
    const float2* sbbf2 = (const float2*)sbb;
    const float4* sdw4  = (const float4*)sdw;
    const float4* sdb4  = (const float4*)sdb;

    for (int it = 0; it < 2; it++){
        const int g = blockIdx.x * 16 + warp * 2 + it;

        const float4* bd4 = (const float4*)(box + (size_t)g * 12);
        float4 rA = __ldg(bd4), rB = __ldg(bd4+1), rC = __ldg(bd4+2);

        float c0[4], c1[4];
        c0[0]=rA.x/640.0f; c0[1]=rA.y/400.0f; c0[2]=rA.z/640.0f; c0[3]=rA.w/400.0f;
        c1[0]=rB.z/640.0f; c1[1]=rB.w/400.0f; c1[2]=rC.x/640.0f; c1[3]=rC.y/400.0f;
        float cat0=rB.x, conf0=rB.y, cat1=rC.z, conf1=rC.w;

        float s0 = ((c0[0]+c0[1])+c0[2])+c0[3];
        float s1 = ((c1[0]+c1[1])+c1[2])+c1[3];
        float p0 = (s0 != 0.0f) ? 1.0f : 0.0f;
        float p1 = (s1 != 0.0f) ? 1.0f : 0.0f;
        const bool swp = (cat1 + (1.0f-p1)*1000.0f) < (cat0 + (1.0f-p0)*1000.0f);

        float sc[2][4], scat[2], sconf[2], spres[2];
#pragma unroll
        for (int k = 0; k < 4; k++){
            sc[0][k] = swp ? c1[k] : c0[k];
            sc[1][k] = swp ? c0[k] : c1[k];
        }
        scat[0]=swp?cat1:cat0;   scat[1]=swp?cat0:cat1;
        sconf[0]=swp?conf1:conf0; sconf[1]=swp?conf0:conf1;
        spres[0]=swp?p1:p0;       spres[1]=swp?p0:p1;

        float cxs[2], cys[2];
#pragma unroll
        for (int s = 0; s < 2; s++){
            float x1=sc[s][0], y1=sc[s][1], x2=sc[s][2], y2=sc[s][3];
            float w=x2-x1, h=y2-y1;
            float cx=(x1+x2)*0.5f, cy=(y1+y2)*0.5f;
            cxs[s]=cx; cys[s]=cy;
            float feat[10] = {x1,y1,x2,y2,w,h,cx,cy,w*h,w/(h+1e-6f)};

            float2 v[4];
#pragma unroll
            for (int q = 0; q < 4; q++){
                int ci = lane + 32*q;                  // float2 index; cols 2ci,2ci+1
                float2 a = sb1f2[ci];
#pragma unroll
                for (int f = 0; f < 10; f++){
                    float2 w2 = sW1f2[f*128 + ci];
                    a.x = fmaf(feat[f], w2.x, a.x);
                    a.y = fmaf(feat[f], w2.y, a.y);
                }
                v[q] = a;
            }
            float sum = 0.f;
#pragma unroll
            for (int q = 0; q < 4; q++) sum += v[q].x + v[q].y;
#pragma unroll
            for (int o = 16; o; o >>= 1) sum += __shfl_xor_sync(0xffffffffu, sum, o);
            float mu = sum * (1.0f/256.0f);

            float var = 0.f;
#pragma unroll
            for (int q = 0; q < 4; q++){
                v[q].x -= mu; v[q].y -= mu;
                var = fmaf(v[q].x, v[q].x, var);
                var = fmaf(v[q].y, v[q].y, var);
            }
#pragma unroll
            for (int o = 16; o; o >>= 1) var += __shfl_xor_sync(0xffffffffu, var, o);
            float rs = rsqrtf(var * (1.0f/256.0f) + 1e-5f);

            const size_t m = (size_t)(2*g + s);
            __half2* hrow = (__half2*)(g_Hh + m*256);
#pragma unroll
            for (int q = 0; q < 4; q++){
                int ci = lane + 32*q;
                float2 gb = sgf2[ci], bb2 = sbbf2[ci];
                float y0 = gelu_exact(v[q].x * rs * gb.x + bb2.x);
                float y1 = gelu_exact(v[q].y * rs * gb.y + bb2.y);
                hrow[ci] = __floats2half2_rn(y0, y1);
            }
        }

        float dx = cxs[0]-cxs[1], dy = cys[0]-cys[1];
        float dist = sqrtf(dx*dx + dy*dy);
        const int bI = g / (NB_T*NB_NC);
        const int rem = g % (NB_T*NB_NC);
        float4* orow4 = (float4*)(out + ((size_t)bI * 1800 + rem) * 512);
#pragma unroll
        for (int jj = 0; jj < 4; jj++){
            int ci = lane + 32*jj;
            float4 w4 = sdw4[ci], b4 = sdb4[ci];
            float4 r4;
            r4.x = fmaf(dist, w4.x, b4.x);
            r4.y = fmaf(dist, w4.y, b4.y);
            r4.z = fmaf(dist, w4.z, b4.z);
            r4.w = fmaf(dist, w4.w, b4.w);
            orow4[ci] = r4;
        }
        if (lane < 2){
            float* mp = g_meta + (size_t)(2*g + lane) * 8;
            mp[0]=scat[lane]; mp[1]=sconf[lane]; mp[2]=cxs[lane];
            mp[3]=cys[lane];  mp[4]=spres[lane];
        }
    }
}

// ---------------------------------------------------------------------------
// k_gemm: fp16 mma m16n8k16 + ldmatrix. CTA tile 128x128, warp tile 64x32
// (2M x 4N warps), BK=32, 3-stage cp.async, 2 CTAs/SM, one sync per iter.
// ---------------------------------------------------------------------------
#define BK 32
#define RST 40                             /* row stride halves (80 B) */
#define STG_HALVES (256*RST)               /* A 128 rows + B 128 rows = 10240 */

__device__ __forceinline__ void mma_f16(float* d, const uint32_t* a, const uint32_t* b){
    asm volatile(
        "mma.sync.aligned.m16n8k16.row.col.f32.f16.f16.f32 "
        "{%0,%1,%2,%3}, {%4,%5,%6,%7}, {%8,%9}, {%0,%1,%2,%3};\n"
        : "+f"(d[0]), "+f"(d[1]), "+f"(d[2]), "+f"(d[3])
        : "r"(a[0]), "r"(a[1]), "r"(a[2]), "r"(a[3]), "r"(b[0]), "r"(b[1]));
}

__global__ __launch_bounds__(256, 2) void k_gemm(
    const float* __restrict__ b2,
    const float* __restrict__ conf_w, const float* __restrict__ conf_b,
    const float* __restrict__ center_w, const float* __restrict__ center_b,
    const float* __restrict__ missing,
    const float* __restrict__ cat_table, const float* __restrict__ cam_table,
    const float* __restrict__ scalep,
    float* __restrict__ out)
{
    extern __shared__ __align__(16) __half sm[];   // 3 stages x 10240 halves

    const int tid  = threadIdx.x;
    const int lane = tid & 31;
    const int warp = tid >> 5;
    const int wm   = warp & 1;      // 2 warps along M (64 rows each)
    const int wn   = warp >> 1;     // 4 warps along N (32 cols each)
    const int gid  = lane >> 2;
    const int tig  = lane & 3;

    const int n0 = blockIdx.x * 128;
    const int m0 = blockIdx.y * 128;

    const int a_row_sel = (lane & 7) + ((lane >> 3) & 1) * 8;
    const int a_col_sel = ((lane >> 4) & 1) * 8;
    const int b_row_sel = (lane & 7) + ((lane >> 4) & 1) * 8;
    const int b_col_sel = ((lane >> 3) & 1) * 8;

    auto load_stage = [&](int s, int ko){
        uint32_t base = smem_u32(sm + s * STG_HALVES);
#pragma unroll
        for (int u = 0; u < 2; u++){                 // A: 512 x 16B chunks
            int c = tid + u*256;
            int row = c >> 2, seg = c & 3;
            const __half* src = g_Hh + (size_t)(m0 + row) * 256 + ko + seg*8;
            CP16(base + row*80 + seg*16, src);
        }
#pragma unroll
        for (int u = 0; u < 2; u++){                 // B: 512 x 16B chunks
            int c = tid + u*256;
            int n = c >> 2, seg = c & 3;
            const __half* src = g_W2h + (size_t)(n0 + n) * 256 + ko + seg*8;
            CP16(base + (128 + n)*80 + seg*16, src);
        }
    };

    float acc[4][4][4];
#pragma unroll
    for (int i = 0; i < 4; i++)
#pragma unroll
        for (int j = 0; j < 4; j++)
#pragma unroll
            for (int k = 0; k < 4; k++) acc[i][j][k] = 0.0f;

    load_stage(0, 0);  CPCOMMIT();
    load_stage(1, BK); CPCOMMIT();

    for (int k = 0; k < 8; k++){
        CPWAIT1();
        __syncthreads();
        if (k + 2 < 8) load_stage((k + 2) % 3, (k + 2) * BK);
        CPCOMMIT();

        const uint32_t s32 = smem_u32(sm + (k % 3) * STG_HALVES);

#pragma unroll
        for (int ks = 0; ks < 2; ks++){
            const int kk = ks * 16;
            uint32_t af[4][4];
#pragma unroll
            for (int mi = 0; mi < 4; mi++){
                int row = wm*64 + mi*16 + a_row_sel;
                ldsm_x4(af[mi], s32 + (row*RST + kk + a_col_sel)*2);
            }
            uint32_t bf[4][2];
#pragma unroll
            for (int nio = 0; nio < 2; nio++){
                uint32_t r[4];
                int row = 128 + wn*32 + nio*16 + b_row_sel;
                ldsm_x4(r, s32 + (row*RST + kk + b_col_sel)*2);
                bf[nio*2  ][0] = r[0]; bf[nio*2  ][1] = r[1];
                bf[nio*2+1][0] = r[2]; bf[nio*2+1][1] = r[3];
            }
#pragma unroll
            for (int mi = 0; mi < 4; mi++)
#pragma unroll
                for (int ni = 0; ni < 4; ni++)
                    mma_f16(acc[mi][ni], af[mi], bf[ni]);
        }
    }
    __syncthreads();

    // ---- epilogue tables (alias pipeline smem) ----
    float* s_base9 = (float*)sm;          // 9*128
    float* s_cw    = s_base9 + 9*128;     // 128 each
    float* s_c0    = s_cw + 128;
    float* s_c1    = s_c0 + 128;
    float* s_miss  = s_c1 + 128;
    for (int i = tid; i < 9*128; i += 256){
        int cc = i >> 7, dl = i & 127, d = n0 + dl;
        s_base9[i] = b2[d] + conf_b[d] + center_b[d]
                   + cat_table[(cc/3)*512 + d] + cam_table[(cc%3)*512 + d];
    }
    if (tid < 128){
        int d = n0 + tid;
        s_cw[tid]   = conf_w[d];
        s_c0[tid]   = center_w[d];
        s_c1[tid]   = center_w[512 + d];
        s_miss[tid] = missing[d];
    }
    __syncthreads();

    const float scaleV = *scalep;
#pragma unroll
    for (int mi = 0; mi < 4; mi++){
#pragma unroll
        for (int h = 0; h < 2; h++){
            int m = m0 + wm*64 + mi*16 + gid + h*8;
            const float* mp = g_meta + (size_t)m * 8;
            float cat = mp[0], conf = mp[1], cxv = mp[2], cyv = mp[3], pres = mp[4];
            int cc  = ((int)cat)*3 + ((m >> 1) % 3);
            int bI  = m / 1200;
            int rem = m % 1200;
            float* orow = out + ((size_t)bI*1800 + 600 + rem) * 512 + n0;
            const float* bsr = s_base9 + cc*128;
#pragma unroll
            for (int ni = 0; ni < 4; ni++){
                int dl = wn*32 + ni*8 + tig*2;
                float v0 = acc[mi][ni][h*2 + 0];
                float v1 = acc[mi][ni][h*2 + 1];
                v0 = (v0 + bsr[dl]   + conf*s_cw[dl]   + cxv*s_c0[dl]   + cyv*s_c1[dl])   * scaleV;
                v1 = (v1 + bsr[dl+1] + conf*s_cw[dl+1] + cxv*s_c0[dl+1] + cyv*s_c1[dl+1]) * scaleV;
                if (pres == 0.0f){ v0 = s_miss[dl]; v1 = s_miss[dl+1]; }
                float2 w2; w2.x = v0; w2.y = v1;
                *reinterpret_cast<float2*>(orow + dl) = w2;
            }
        }
    }
}

// ---------------------------------------------------------------------------
extern "C" void kernel_launch(void* const* d_in, const int* in_sizes, int n_in,
                              void* d_out, int out_size)
{
    const float* box        = (const float*)d_in[0];
    const float* cat_table  = (const float*)d_in[1];
    const float* W1         = (const float*)d_in[2];
    const float* b1         = (const float*)d_in[3];
    const float* lng        = (const float*)d_in[4];
    const float* lnb        = (const float*)d_in[5];
    const float* W2         = (const float*)d_in[6];
    const float* b2         = (const float*)d_in[7];
    const float* conf_w     = (const float*)d_in[8];
    const float* conf_b     = (const float*)d_in[9];
    const float* center_w   = (const float*)d_in[10];
    const float* center_b   = (const float*)d_in[11];
    const float* missing    = (const float*)d_in[12];
    const float* dist_w     = (const float*)d_in[13];
    const float* dist_b     = (const float*)d_in[14];
    const float* cam_table  = (const float*)d_in[15];
    const float* scalep     = (const float*)d_in[16];
    float* out = (float*)d_out;

    const int dyn_smem = 3 * STG_HALVES * 2;   // 61440 B
    cudaFuncSetAttribute(k_gemm, cudaFuncAttributeMaxDynamicSharedMemorySize, dyn_smem);

    k_features<<<4800, 256>>>(box, W1, b1, lng, lnb, dist_w, dist_b, W2, out);
    k_gemm<<<dim3(4, 1200), 256, dyn_smem>>>(b2, conf_w, conf_b, center_w, center_b,
                                             missing, cat_table, cam_table, scalep, out);
}

// round 7
// speedup vs baseline: 2.5506x; 1.3215x over previous
#include <cuda_runtime.h>
#include <cuda_fp16.h>
#include <cstdint>

#define NB_T 200
#define NB_NC 3
#define NGROUP 76800
#define NBOX   153600

// Scratch
__device__ __half g_Hh[(size_t)NBOX * 256];    // activations [M,K] row-major fp16
__device__ __half g_W2h[512 * 256];            // W2 transposed -> [N,K] row-major fp16
__device__ float  g_meta[(size_t)NBOX * 8];

__device__ __forceinline__ uint32_t smem_u32(const void* p){
    return (uint32_t)__cvta_generic_to_shared(p);
}

// Fast erf: Abramowitz-Stegun 7.1.26, |abs err| <= 1.5e-7
__device__ __forceinline__ float fast_erf(float x){
    float ax = fabsf(x);
    float t  = __frcp_rn(fmaf(0.3275911f, ax, 1.0f));
    float p  = fmaf(t, 1.061405429f, -1.453152027f);
    p = fmaf(t, p, 1.421413741f);
    p = fmaf(t, p, -0.284496736f);
    p = fmaf(t, p, 0.254829592f);
    p = p * t;
    float e  = __expf(-ax*ax);
    float r  = fmaf(-p, e, 1.0f);
    return copysignf(r, x);
}
__device__ __forceinline__ float gelu_fast(float x){
    return 0.5f * x * (1.0f + fast_erf(x * 0.70710678118654752440f));
}

#define CP16(dst, src) asm volatile("cp.async.cg.shared.global [%0], [%1], 16;\n" :: "r"(dst), "l"(src))
#define CPCOMMIT()     asm volatile("cp.async.commit_group;\n" ::: "memory")
#define CPWAIT2()      asm volatile("cp.async.wait_group 2;\n" ::: "memory")

__device__ __forceinline__ void ldsm_x4(uint32_t* r, uint32_t addr){
    asm volatile("ldmatrix.sync.aligned.m8n8.x4.shared.b16 {%0,%1,%2,%3}, [%4];\n"
        : "=r"(r[0]), "=r"(r[1]), "=r"(r[2]), "=r"(r[3]) : "r"(addr));
}

// ---------------------------------------------------------------------------
// k_features: 4800 blocks, warp handles 2 groups; both boxes of a group
// processed interleaved for ILP. Fast-erf GELU. Blocks < 512 transpose W2.
// ---------------------------------------------------------------------------
__global__ __launch_bounds__(256) void k_features(
    const float* __restrict__ box,
    const float* __restrict__ W1, const float* __restrict__ b1,
    const float* __restrict__ lng, const float* __restrict__ lnb,
    const float* __restrict__ dist_w, const float* __restrict__ dist_b,
    const float* __restrict__ W2,
    float* __restrict__ out)
{
    __shared__ __align__(16) float sW1[2560];
    __shared__ __align__(16) float sb1[256], sg[256], sbb[256];
    __shared__ __align__(16) float sdw[512], sdb[512];
    const int tid  = threadIdx.x;
    const int lane = tid & 31;
    const int warp = tid >> 5;

    if (blockIdx.x < 512){                       // merged W2 transpose
        int idx = blockIdx.x * 256 + tid;
        int k = idx >> 9, n = idx & 511;
        g_W2h[n * 256 + k] = __float2half(W2[idx]);
    }

    for (int i = tid; i < 2560; i += 256) sW1[i] = W1[i];
    if (tid < 256){ sb1[tid] = b1[tid]; sg[tid] = lng[tid]; sbb[tid] = lnb[tid]; }
    for (int i = tid; i < 512; i += 256){ sdw[i] = dist_w[i]; sdb[i] = dist_b[i]; }
    __syncthreads();

    const float2* sW1f2 = (const float2*)sW1;
    const float2* sb1f2 = (const float2*)sb1;
    const float2* sgf2  = (const float2*)sg;
    const float2* sbbf2 = (const float2*)sbb;
    const float4* sdw4  = (const float4*)sdw;
    const float4* sdb4  = (const float4*)sdb;

    for (int it = 0; it < 2; it++){
        const int g = blockIdx.x * 16 + warp * 2 + it;

        const float4* bd4 = (const float4*)(box + (size_t)g * 12);
        float4 rA = __ldg(bd4), rB = __ldg(bd4+1), rC = __ldg(bd4+2);

        float c0[4], c1[4];
        c0[0]=rA.x/640.0f; c0[1]=rA.y/400.0f; c0[2]=rA.z/640.0f; c0[3]=rA.w/400.0f;
        c1[0]=rB.z/640.0f; c1[1]=rB.w/400.0f; c1[2]=rC.x/640.0f; c1[3]=rC.y/400.0f;
        float cat0=rB.x, conf0=rB.y, cat1=rC.z, conf1=rC.w;

        float s0 = ((c0[0]+c0[1])+c0[2])+c0[3];
        float s1 = ((c1[0]+c1[1])+c1[2])+c1[3];
        float p0 = (s0 != 0.0f) ? 1.0f : 0.0f;
        float p1 = (s1 != 0.0f) ? 1.0f : 0.0f;
        const bool swp = (cat1 + (1.0f-p1)*1000.0f) < (cat0 + (1.0f-p0)*1000.0f);

        float sc[2][4], scat[2], sconf[2], spres[2];
#pragma unroll
        for (int k = 0; k < 4; k++){
            sc[0][k] = swp ? c1[k] : c0[k];
            sc[1][k] = swp ? c0[k] : c1[k];
        }
        scat[0]=swp?cat1:cat0;   scat[1]=swp?cat0:cat1;
        sconf[0]=swp?conf1:conf0; sconf[1]=swp?conf0:conf1;
        spres[0]=swp?p1:p0;       spres[1]=swp?p0:p1;

        // features for both boxes
        float feat[2][10], cxs[2], cys[2];
#pragma unroll
        for (int s = 0; s < 2; s++){
            float x1=sc[s][0], y1=sc[s][1], x2=sc[s][2], y2=sc[s][3];
            float w=x2-x1, h=y2-y1;
            float cx=(x1+x2)*0.5f, cy=(y1+y2)*0.5f;
            cxs[s]=cx; cys[s]=cy;
            feat[s][0]=x1; feat[s][1]=y1; feat[s][2]=x2; feat[s][3]=y2;
            feat[s][4]=w;  feat[s][5]=h;  feat[s][6]=cx; feat[s][7]=cy;
            feat[s][8]=w*h; feat[s][9]=w/(h+1e-6f);
        }

        // matvec, both boxes interleaved
        float2 va[4], vb[4];
#pragma unroll
        for (int q = 0; q < 4; q++){
            int ci = lane + 32*q;
            float2 bias = sb1f2[ci];
            float2 a0 = bias, a1 = bias;
#pragma unroll
            for (int f = 0; f < 10; f++){
                float2 w2 = sW1f2[f*128 + ci];
                a0.x = fmaf(feat[0][f], w2.x, a0.x);
                a0.y = fmaf(feat[0][f], w2.y, a0.y);
                a1.x = fmaf(feat[1][f], w2.x, a1.x);
                a1.y = fmaf(feat[1][f], w2.y, a1.y);
            }
            va[q] = a0; vb[q] = a1;
        }

        // means (interleaved reductions)
        float su0 = 0.f, su1 = 0.f;
#pragma unroll
        for (int q = 0; q < 4; q++){ su0 += va[q].x + va[q].y; su1 += vb[q].x + vb[q].y; }
#pragma unroll
        for (int o = 16; o; o >>= 1){
            su0 += __shfl_xor_sync(0xffffffffu, su0, o);
            su1 += __shfl_xor_sync(0xffffffffu, su1, o);
        }
        float mu0 = su0 * (1.0f/256.0f), mu1 = su1 * (1.0f/256.0f);

        float vr0 = 0.f, vr1 = 0.f;
#pragma unroll
        for (int q = 0; q < 4; q++){
            va[q].x -= mu0; va[q].y -= mu0;
            vb[q].x -= mu1; vb[q].y -= mu1;
            vr0 = fmaf(va[q].x, va[q].x, vr0); vr0 = fmaf(va[q].y, va[q].y, vr0);
            vr1 = fmaf(vb[q].x, vb[q].x, vr1); vr1 = fmaf(vb[q].y, vb[q].y, vr1);
        }
#pragma unroll
        for (int o = 16; o; o >>= 1){
            vr0 += __shfl_xor_sync(0xffffffffu, vr0, o);
            vr1 += __shfl_xor_sync(0xffffffffu, vr1, o);
        }
        float rs0 = rsqrtf(vr0 * (1.0f/256.0f) + 1e-5f);
        float rs1 = rsqrtf(vr1 * (1.0f/256.0f) + 1e-5f);

        __half2* hrow0 = (__half2*)(g_Hh + (size_t)(2*g + 0)*256);
        __half2* hrow1 = (__half2*)(g_Hh + (size_t)(2*g + 1)*256);
#pragma unroll
        for (int q = 0; q < 4; q++){
            int ci = lane + 32*q;
            float2 gb = sgf2[ci], bb2 = sbbf2[ci];
            float y00 = gelu_fast(va[q].x * rs0 * gb.x + bb2.x);
            float y01 = gelu_fast(va[q].y * rs0 * gb.y + bb2.y);
            float y10 = gelu_fast(vb[q].x * rs1 * gb.x + bb2.x);
            float y11 = gelu_fast(vb[q].y * rs1 * gb.y + bb2.y);
            hrow0[ci] = __floats2half2_rn(y00, y01);
            hrow1[ci] = __floats2half2_rn(y10, y11);
        }

        float dx = cxs[0]-cxs[1], dy = cys[0]-cys[1];
        float dist = sqrtf(dx*dx + dy*dy);
        const int bI = g / (NB_T*NB_NC);
        const int rem = g % (NB_T*NB_NC);
        float4* orow4 = (float4*)(out + ((size_t)bI * 1800 + rem) * 512);
#pragma unroll
        for (int jj = 0; jj < 4; jj++){
            int ci = lane + 32*jj;
            float4 w4 = sdw4[ci], b4 = sdb4[ci];
            float4 r4;
            r4.x = fmaf(dist, w4.x, b4.x);
            r4.y = fmaf(dist, w4.y, b4.y);
            r4.z = fmaf(dist, w4.z, b4.z);
            r4.w = fmaf(dist, w4.w, b4.w);
            orow4[ci] = r4;
        }
        if (lane < 2){
            float* mp = g_meta + (size_t)(2*g + lane) * 8;
            mp[0]=scat[lane]; mp[1]=sconf[lane]; mp[2]=cxs[lane];
            mp[3]=cys[lane];  mp[4]=spres[lane];
        }
    }
}

// ---------------------------------------------------------------------------
// k_gemm: fp16 mma m16n8k16 + ldmatrix. CTA tile 128x128, warp tile 64x32,
// BK=32, 4-stage cp.async pipeline (wait_group 2), 2 CTAs/SM.
// ---------------------------------------------------------------------------
#define BK 32
#define RST 40                             /* row stride halves (80 B) */
#define STG_HALVES (256*RST)               /* 10240 halves = 20480 B */

__device__ __forceinline__ void mma_f16(float* d, const uint32_t* a, const uint32_t* b){
    asm volatile(
        "mma.sync.aligned.m16n8k16.row.col.f32.f16.f16.f32 "
        "{%0,%1,%2,%3}, {%4,%5,%6,%7}, {%8,%9}, {%0,%1,%2,%3};\n"
        : "+f"(d[0]), "+f"(d[1]), "+f"(d[2]), "+f"(d[3])
        : "r"(a[0]), "r"(a[1]), "r"(a[2]), "r"(a[3]), "r"(b[0]), "r"(b[1]));
}

__global__ __launch_bounds__(256, 2) void k_gemm(
    const float* __restrict__ b2,
    const float* __restrict__ conf_w, const float* __restrict__ conf_b,
    const float* __restrict__ center_w, const float* __restrict__ center_b,
    const float* __restrict__ missing,
    const float* __restrict__ cat_table, const float* __restrict__ cam_table,
    const float* __restrict__ scalep,
    float* __restrict__ out)
{
    extern __shared__ __align__(16) __half sm[];   // 4 stages x 10240 halves

    const int tid  = threadIdx.x;
    const int lane = tid & 31;
    const int warp = tid >> 5;
    const int wm   = warp & 1;      // 2 warps along M (64 rows each)
    const int wn   = warp >> 1;     // 4 warps along N (32 cols each)
    const int gid  = lane >> 2;
    const int tig  = lane & 3;

    const int n0 = blockIdx.x * 128;
    const int m0 = blockIdx.y * 128;

    const int a_row_sel = (lane & 7) + ((lane >> 3) & 1) * 8;
    const int a_col_sel = ((lane >> 4) & 1) * 8;
    const int b_row_sel = (lane & 7) + ((lane >> 4) & 1) * 8;
    const int b_col_sel = ((lane >> 3) & 1) * 8;

    auto load_stage = [&](int s, int ko){
        uint32_t base = smem_u32(sm + s * STG_HALVES);
#pragma unroll
        for (int u = 0; u < 2; u++){                 // A: 512 x 16B chunks
            int c = tid + u*256;
            int row = c >> 2, seg = c & 3;
            const __half* src = g_Hh + (size_t)(m0 + row) * 256 + ko + seg*8;
            CP16(base + row*80 + seg*16, src);
        }
#pragma unroll
        for (int u = 0; u < 2; u++){                 // B: 512 x 16B chunks
            int c = tid + u*256;
            int n = c >> 2, seg = c & 3;
            const __half* src = g_W2h + (size_t)(n0 + n) * 256 + ko + seg*8;
            CP16(base + (128 + n)*80 + seg*16, src);
        }
    };

    float acc[4][4][4];
#pragma unroll
    for (int i = 0; i < 4; i++)
#pragma unroll
        for (int j = 0; j < 4; j++)
#pragma unroll
            for (int k = 0; k < 4; k++) acc[i][j][k] = 0.0f;

    load_stage(0, 0);    CPCOMMIT();
    load_stage(1, BK);   CPCOMMIT();
    load_stage(2, 2*BK); CPCOMMIT();

    for (int k = 0; k < 8; k++){
        CPWAIT2();
        __syncthreads();
        if (k + 3 < 8) load_stage((k + 3) & 3, (k + 3) * BK);
        CPCOMMIT();

        const uint32_t s32 = smem_u32(sm + (k & 3) * STG_HALVES);

#pragma unroll
        for (int ks = 0; ks < 2; ks++){
            const int kk = ks * 16;
            uint32_t af[4][4];
#pragma unroll
            for (int mi = 0; mi < 4; mi++){
                int row = wm*64 + mi*16 + a_row_sel;
                ldsm_x4(af[mi], s32 + (row*RST + kk + a_col_sel)*2);
            }
            uint32_t bf[4][2];
#pragma unroll
            for (int nio = 0; nio < 2; nio++){
                uint32_t r[4];
                int row = 128 + wn*32 + nio*16 + b_row_sel;
                ldsm_x4(r, s32 + (row*RST + kk + b_col_sel)*2);
                bf[nio*2  ][0] = r[0]; bf[nio*2  ][1] = r[1];
                bf[nio*2+1][0] = r[2]; bf[nio*2+1][1] = r[3];
            }
#pragma unroll
            for (int mi = 0; mi < 4; mi++)
#pragma unroll
                for (int ni = 0; ni < 4; ni++)
                    mma_f16(acc[mi][ni], af[mi], bf[ni]);
        }
    }
    __syncthreads();

    // ---- epilogue tables (alias pipeline smem) ----
    float* s_base9 = (float*)sm;          // 9*128
    float* s_cw    = s_base9 + 9*128;     // 128 each
    float* s_c0    = s_cw + 128;
    float* s_c1    = s_c0 + 128;
    float* s_miss  = s_c1 + 128;
    for (int i = tid; i < 9*128; i += 256){
        int cc = i >> 7, dl = i & 127, d = n0 + dl;
        s_base9[i] = b2[d] + conf_b[d] + center_b[d]
                   + cat_table[(cc/3)*512 + d] + cam_table[(cc%3)*512 + d];
    }
    if (tid < 128){
        int d = n0 + tid;
        s_cw[tid]   = conf_w[d];
        s_c0[tid]   = center_w[d];
        s_c1[tid]   = center_w[512 + d];
        s_miss[tid] = missing[d];
    }
    __syncthreads();

    const float scaleV = *scalep;
#pragma unroll
    for (int mi = 0; mi < 4; mi++){
#pragma unroll
        for (int h = 0; h < 2; h++){
            int m = m0 + wm*64 + mi*16 + gid + h*8;
            const float* mp = g_meta + (size_t)m * 8;
            float cat = mp[0], conf = mp[1], cxv = mp[2], cyv = mp[3], pres = mp[4];
            int cc  = ((int)cat)*3 + ((m >> 1) % 3);
            int bI  = m / 1200;
            int rem = m % 1200;
            float* orow = out + ((size_t)bI*1800 + 600 + rem) * 512 + n0;
            const float* bsr = s_base9 + cc*128;
#pragma unroll
            for (int ni = 0; ni < 4; ni++){
                int dl = wn*32 + ni*8 + tig*2;
                float v0 = acc[mi][ni][h*2 + 0];
                float v1 = acc[mi][ni][h*2 + 1];
                v0 = (v0 + bsr[dl]   + conf*s_cw[dl]   + cxv*s_c0[dl]   + cyv*s_c1[dl])   * scaleV;
                v1 = (v1 + bsr[dl+1] + conf*s_cw[dl+1] + cxv*s_c0[dl+1] + cyv*s_c1[dl+1]) * scaleV;
                if (pres == 0.0f){ v0 = s_miss[dl]; v1 = s_miss[dl+1]; }
                float2 w2; w2.x = v0; w2.y = v1;
                *reinterpret_cast<float2*>(orow + dl) = w2;
            }
        }
    }
}

// ---------------------------------------------------------------------------
extern "C" void kernel_launch(void* const* d_in, const int* in_sizes, int n_in,
                              void* d_out, int out_size)
{
    const float* box        = (const float*)d_in[0];
    const float* cat_table  = (const float*)d_in[1];
    const float* W1         = (const float*)d_in[2];
    const float* b1         = (const float*)d_in[3];
    const float* lng        = (const float*)d_in[4];
    const float* lnb        = (const float*)d_in[5];
    const float* W2         = (const float*)d_in[6];
    const float* b2         = (const float*)d_in[7];
    const float* conf_w     = (const float*)d_in[8];
    const float* conf_b     = (const float*)d_in[9];
    const float* center_w   = (const float*)d_in[10];
    const float* center_b   = (const float*)d_in[11];
    const float* missing    = (const float*)d_in[12];
    const float* dist_w     = (const float*)d_in[13];
    const float* dist_b     = (const float*)d_in[14];
    const float* cam_table  = (const float*)d_in[15];
    const float* scalep     = (const float*)d_in[16];
    float* out = (float*)d_out;

    const int dyn_smem = 4 * STG_HALVES * 2;   // 81920 B
    cudaFuncSetAttribute(k_gemm, cudaFuncAttributeMaxDynamicSharedMemorySize, dyn_smem);

    k_features<<<4800, 256>>>(box, W1, b1, lng, lnb, dist_w, dist_b, W2, out);
    k_gemm<<<dim3(4, 1200), 256, dyn_smem>>>(b2, conf_w, conf_b, center_w, center_b,
                                             missing, cat_table, cam_table, scalep, out);
}